// round 1
// baseline (speedup 1.0000x reference)
#include <cuda_runtime.h>
#include <cuda_bf16.h>
#include <cstdint>

// Problem constants (fixed shapes from reference)
#define BATCH 2
#define SEQ 2048
#define IN_DIM 1024
#define HID_DIM 1024
#define NHEAD 16
#define HDIM 64

// Scratch (allocation-free rule: __device__ globals)
__device__ float g_Q[BATCH * SEQ * HID_DIM];   // 16 MB
__device__ float g_K[BATCH * SEQ * HDIM];      // 1 MB
__device__ float g_V[BATCH * SEQ * HDIM];      // 1 MB
__device__ float g_O[BATCH * SEQ * HID_DIM];   // 16 MB

// ---------------------------------------------------------------------------
// Generic tiled fp32 GEMM with bias: C[M,N] = A[M,K] @ B[K,N] + bias[N]
// A row-major, B row-major. M%BM==0, N%BN==0, K%BK==0 (true for our shapes).
// ---------------------------------------------------------------------------
template <int BM, int BN, int BK, int TM, int TN>
__global__ __launch_bounds__(256) void gemm_bias_kernel(
    const float* __restrict__ A, const float* __restrict__ B,
    const float* __restrict__ bias, float* __restrict__ C,
    int M, int N, int K)
{
    static_assert((BM / TM) * (BN / TN) == 256, "256 threads");
    __shared__ float As[BK][BM + 4];
    __shared__ float Bs[BK][BN];

    const int tid = threadIdx.x;
    const int tx = tid % (BN / TN);
    const int ty = tid / (BN / TN);
    const int m0 = blockIdx.y * BM;
    const int n0 = blockIdx.x * BN;

    // A tile loading: BM*BK floats as float4 along K
    constexpr int A_THREADS = BM * BK / 4;
    const int ar = tid / (BK / 4);
    const int ac = (tid % (BK / 4)) * 4;
    // B tile loading: BK*BN floats as float4 along N
    constexpr int B_THREADS = BK * BN / 4;
    const int br = tid / (BN / 4);
    const int bc = (tid % (BN / 4)) * 4;

    float acc[TM][TN] = {};

    for (int k0 = 0; k0 < K; k0 += BK) {
        if (tid < A_THREADS) {
            float4 v = *(const float4*)(A + (size_t)(m0 + ar) * K + k0 + ac);
            As[ac + 0][ar] = v.x;
            As[ac + 1][ar] = v.y;
            As[ac + 2][ar] = v.z;
            As[ac + 3][ar] = v.w;
        }
        if (tid < B_THREADS) {
            *(float4*)&Bs[br][bc] = *(const float4*)(B + (size_t)(k0 + br) * N + n0 + bc);
        }
        __syncthreads();

#pragma unroll
        for (int kk = 0; kk < BK; kk++) {
            float a[TM], b[TN];
#pragma unroll
            for (int i = 0; i < TM; i++) a[i] = As[kk][ty * TM + i];
#pragma unroll
            for (int j = 0; j < TN; j++) b[j] = Bs[kk][tx * TN + j];
#pragma unroll
            for (int i = 0; i < TM; i++)
#pragma unroll
                for (int j = 0; j < TN; j++)
                    acc[i][j] = fmaf(a[i], b[j], acc[i][j]);
        }
        __syncthreads();
    }

#pragma unroll
    for (int i = 0; i < TM; i++) {
        const int row = m0 + ty * TM + i;
#pragma unroll
        for (int j = 0; j < TN; j += 4) {
            const int col = n0 + tx * TN + j;
            float4 o;
            o.x = acc[i][j + 0] + bias[col + 0];
            o.y = acc[i][j + 1] + bias[col + 1];
            o.z = acc[i][j + 2] + bias[col + 2];
            o.w = acc[i][j + 3] + bias[col + 3];
            *(float4*)(C + (size_t)row * N + col) = o;
        }
    }
}

// ---------------------------------------------------------------------------
// Fused MQA attention (flash-style, fp32).
// Q: [B,S,H*D] (head h at cols h*64..), K/V: [B,S,D], O: [B,S,H*D].
// Block = (q-tile 64, head, batch), 256 threads, 32 keys per inner iter.
// ---------------------------------------------------------------------------
__global__ __launch_bounds__(256) void mqa_attn_kernel(
    const float* __restrict__ Q, const float* __restrict__ Kp,
    const float* __restrict__ Vp, float* __restrict__ O)
{
    constexpr int QB = 64;
    constexpr int KBLK = 32;
    constexpr int D = HDIM;

    __shared__ float q_s[D][QB + 1];      // transposed: [dim][query]
    __shared__ float k_s[D][KBLK + 1];    // transposed: [dim][key]
    __shared__ float v_s[KBLK][D + 4];    // [key][dim]
    __shared__ float s_s[QB][KBLK + 1];   // scores / probabilities
    __shared__ float m_s[QB], l_s[QB], alpha_s[QB];

    const int tid = threadIdx.x;
    const int qb = blockIdx.x;
    const int h = blockIdx.y;
    const int b = blockIdx.z;
    const int q0 = qb * QB;
    const float scale = 1.0f / 32.0f;  // 1/sqrt(HID_DIM)

    // Load Q tile (scaled, transposed)
    {
        const float* qbase = Q + ((size_t)b * SEQ + q0) * HID_DIM + h * HDIM;
        const int r = tid / 16;
        const int c = (tid % 16) * 4;
        for (int rr = r; rr < QB; rr += 16) {
            float4 v = *(const float4*)(qbase + (size_t)rr * HID_DIM + c);
            q_s[c + 0][rr] = v.x * scale;
            q_s[c + 1][rr] = v.y * scale;
            q_s[c + 2][rr] = v.z * scale;
            q_s[c + 3][rr] = v.w * scale;
        }
    }
    if (tid < QB) { m_s[tid] = -1e30f; l_s[tid] = 0.0f; }

    float acc[4][4] = {};
    const int sy = tid / 16, sx = tid % 16;  // scores: rows sy*4+i, cols sx*2+j
    const int oy = tid / 16, ox = tid % 16;  // pv: rows oy*4+i, dims ox*4+j

    for (int k0 = 0; k0 < SEQ; k0 += KBLK) {
        __syncthreads();  // prior PV done reading k_s/v_s/s_s
        // Load K (transposed) + V tile
        {
            const float* kp = Kp + ((size_t)b * SEQ + k0) * D;
            const float* vp = Vp + ((size_t)b * SEQ + k0) * D;
            const int r = tid / 16;
            const int c = (tid % 16) * 4;
            for (int rr = r; rr < KBLK; rr += 16) {
                float4 kv = *(const float4*)(kp + (size_t)rr * D + c);
                k_s[c + 0][rr] = kv.x;
                k_s[c + 1][rr] = kv.y;
                k_s[c + 2][rr] = kv.z;
                k_s[c + 3][rr] = kv.w;
                *(float4*)&v_s[rr][c] = *(const float4*)(vp + (size_t)rr * D + c);
            }
        }
        __syncthreads();

        // Scores: S(64x32) = Qs^T(64xD) @ Ks(DxKBLK)
        float sc[4][2] = {};
#pragma unroll 16
        for (int kk = 0; kk < D; kk++) {
            float a[4], bb[2];
#pragma unroll
            for (int i = 0; i < 4; i++) a[i] = q_s[kk][sy * 4 + i];
#pragma unroll
            for (int j = 0; j < 2; j++) bb[j] = k_s[kk][sx * 2 + j];
#pragma unroll
            for (int i = 0; i < 4; i++)
#pragma unroll
                for (int j = 0; j < 2; j++)
                    sc[i][j] = fmaf(a[i], bb[j], sc[i][j]);
        }
#pragma unroll
        for (int i = 0; i < 4; i++)
#pragma unroll
            for (int j = 0; j < 2; j++)
                s_s[sy * 4 + i][sx * 2 + j] = sc[i][j];
        __syncthreads();

        // Online softmax: one thread per query row
        if (tid < QB) {
            const float m_old = m_s[tid];
            float mx = m_old;
#pragma unroll
            for (int j = 0; j < KBLK; j++) mx = fmaxf(mx, s_s[tid][j]);
            const float alpha = expf(m_old - mx);
            float sum = 0.0f;
#pragma unroll
            for (int j = 0; j < KBLK; j++) {
                const float p = expf(s_s[tid][j] - mx);
                s_s[tid][j] = p;
                sum += p;
            }
            m_s[tid] = mx;
            l_s[tid] = l_s[tid] * alpha + sum;
            alpha_s[tid] = alpha;
        }
        __syncthreads();

        // acc = acc * alpha + P @ V
        float al[4];
#pragma unroll
        for (int i = 0; i < 4; i++) al[i] = alpha_s[oy * 4 + i];
#pragma unroll
        for (int i = 0; i < 4; i++)
#pragma unroll
            for (int j = 0; j < 4; j++)
                acc[i][j] *= al[i];

#pragma unroll 8
        for (int kk = 0; kk < KBLK; kk++) {
            float p[4], vv[4];
#pragma unroll
            for (int i = 0; i < 4; i++) p[i] = s_s[oy * 4 + i][kk];
#pragma unroll
            for (int j = 0; j < 4; j++) vv[j] = v_s[kk][ox * 4 + j];
#pragma unroll
            for (int i = 0; i < 4; i++)
#pragma unroll
                for (int j = 0; j < 4; j++)
                    acc[i][j] = fmaf(p[i], vv[j], acc[i][j]);
        }
    }
    __syncthreads();

    // Write normalized output
    float* obase = O + ((size_t)b * SEQ + q0) * HID_DIM + h * HDIM;
#pragma unroll
    for (int i = 0; i < 4; i++) {
        const int row = oy * 4 + i;
        const float inv = 1.0f / l_s[row];
        float4 o;
        o.x = acc[i][0] * inv;
        o.y = acc[i][1] * inv;
        o.z = acc[i][2] * inv;
        o.w = acc[i][3] * inv;
        *(float4*)(obase + (size_t)row * HID_DIM + ox * 4) = o;
    }
}

// ---------------------------------------------------------------------------
// Launch
// ---------------------------------------------------------------------------
extern "C" void kernel_launch(void* const* d_in, const int* in_sizes, int n_in,
                              void* d_out, int out_size)
{
    const float* query = (const float*)d_in[0];
    const float* key   = (const float*)d_in[1];
    const float* value = (const float*)d_in[2];
    const float* Wq    = (const float*)d_in[3];
    const float* bq    = (const float*)d_in[4];
    const float* Wk    = (const float*)d_in[5];
    const float* bk    = (const float*)d_in[6];
    const float* Wv    = (const float*)d_in[7];
    const float* bv    = (const float*)d_in[8];
    const float* Wo    = (const float*)d_in[9];
    const float* bo    = (const float*)d_in[10];
    float* out = (float*)d_out;

    void *pQ, *pK, *pV, *pO;
    cudaGetSymbolAddress(&pQ, g_Q);
    cudaGetSymbolAddress(&pK, g_K);
    cudaGetSymbolAddress(&pV, g_V);
    cudaGetSymbolAddress(&pO, g_O);

    const int M = BATCH * SEQ;  // 4096

    // Q projection: [4096,1024] @ [1024,1024]
    {
        dim3 grid(HID_DIM / 128, M / 128);
        gemm_bias_kernel<128, 128, 8, 8, 8><<<grid, 256>>>(
            query, Wq, bq, (float*)pQ, M, HID_DIM, IN_DIM);
    }
    // K projection: [4096,1024] @ [1024,64]
    {
        dim3 grid(HDIM / 64, M / 64);
        gemm_bias_kernel<64, 64, 8, 4, 4><<<grid, 256>>>(
            key, Wk, bk, (float*)pK, M, HDIM, IN_DIM);
    }
    // V projection
    {
        dim3 grid(HDIM / 64, M / 64);
        gemm_bias_kernel<64, 64, 8, 4, 4><<<grid, 256>>>(
            value, Wv, bv, (float*)pV, M, HDIM, IN_DIM);
    }
    // Fused MQA attention
    {
        dim3 grid(SEQ / 64, NHEAD, BATCH);
        mqa_attn_kernel<<<grid, 256>>>((const float*)pQ, (const float*)pK,
                                       (const float*)pV, (float*)pO);
    }
    // Output projection: [4096,1024] @ [1024,1024] -> d_out
    {
        dim3 grid(IN_DIM / 128, M / 128);
        gemm_bias_kernel<128, 128, 8, 8, 8><<<grid, 256>>>(
            (const float*)pO, Wo, bo, out, M, IN_DIM, HID_DIM);
    }
}